// round 1
// baseline (speedup 1.0000x reference)
#include <cuda_runtime.h>

// Problem constants
#define BB   8192
#define TT   80
#define HH   100
#define VV   100
#define G4   400      // 4*H
#define BCTA 56       // batch rows per CTA
#define ROWT 14       // row-thread groups (56/4)
#define COLT 25       // col-thread groups (100/4)
#define NTHR 352      // 11 warps (350 active)
#define NACT 350
#define NCTA 147      // ceil(8192/56)

#define SMEM0 ((40000 + 5600) * 4 + 64 * 4)       // Wt0 + h_s + tok
#define SMEM1 ((40000 + 5600 + 5600 + 400) * 4)   // W + h_s + x_s + bias

// ---------------- scratch (device globals; no runtime allocation) ----------
__device__ float g_table0[VV * G4];                 // layer0 input table (incl. bias)
__device__ float g_Wt0 [HH * G4];                   // W_hh0^T  [k][j]
__device__ float g_Wt1i[HH * G4];                   // W_ih1^T  [k][j]
__device__ float g_Wt1h[HH * G4];                   // W_hh1^T  [k][j]
__device__ float g_b1  [G4];                        // b_ih1 + b_hh1
__device__ float g_h1[(size_t)TT * HH * BB + 64];   // layer0 output [t][k][b]
__device__ float g_h2[(size_t)HH * BB + 64];        // layer1 final h [k][b]

// ---------------- activations (accurate fast-math) -------------------------
__device__ __forceinline__ float sig_(float x) {
    return __fdividef(1.f, 1.f + __expf(-x));
}
__device__ __forceinline__ float tanh_(float x) {
    float e = __expf(2.f * x);
    return 1.f - __fdividef(2.f, e + 1.f);
}

// ---------------- prep: transposes + layer0 input table + bias -------------
__global__ void prep_kernel(const float* __restrict__ embed,
                            const float* __restrict__ Wih0,
                            const float* __restrict__ Whh0,
                            const float* __restrict__ bih0,
                            const float* __restrict__ bhh0,
                            const float* __restrict__ Wih1,
                            const float* __restrict__ Whh1,
                            const float* __restrict__ bih1,
                            const float* __restrict__ bhh1) {
    for (int idx = blockIdx.x * blockDim.x + threadIdx.x; idx < HH * G4;
         idx += gridDim.x * blockDim.x) {
        int k = idx / G4;          // 0..99  (also vocab index below)
        int j = idx % G4;          // 0..399
        g_Wt0 [k * G4 + j] = Whh0[j * HH + k];
        g_Wt1i[k * G4 + j] = Wih1[j * HH + k];
        g_Wt1h[k * G4 + j] = Whh1[j * HH + k];
        // layer0 gate-input table: table[v][j] = b_ih0[j]+b_hh0[j] + W_ih0[j,:]·embed[v,:]
        float s = bih0[j] + bhh0[j];
        #pragma unroll
        for (int e = 0; e < 8; e++) s += Wih0[j * 8 + e] * embed[k * 8 + e];
        g_table0[k * G4 + j] = s;
        if (idx < G4) g_b1[idx] = bih1[idx] + bhh1[idx];
    }
}

// ---------------- register-blocked [56,100]x[100,400] accumulate -----------
// acc[g][r][c] += W^T[k][g*100 + tx*4 + c] * in[k][b0 + ty*4 + r]
__device__ __forceinline__ void gemm_acc(const float4* __restrict__ ws4,
                                         const float4* __restrict__ in4,
                                         int ty, int tx, float acc[4][4][4]) {
    #pragma unroll 2
    for (int k = 0; k < HH; k++) {
        float4 h4 = in4[k * ROWT + ty];
        const float4* wr = ws4 + k * 100 + tx;
        float4 wv[4];
        wv[0] = wr[0]; wv[1] = wr[25]; wv[2] = wr[50]; wv[3] = wr[75];
        float hv[4] = {h4.x, h4.y, h4.z, h4.w};
        #pragma unroll
        for (int g = 0; g < 4; g++) {
            #pragma unroll
            for (int r = 0; r < 4; r++) {
                acc[g][r][0] += wv[g].x * hv[r];
                acc[g][r][1] += wv[g].y * hv[r];
                acc[g][r][2] += wv[g].z * hv[r];
                acc[g][r][3] += wv[g].w * hv[r];
            }
        }
    }
}

// ---------------- LSTM cell elementwise + h store to smem ------------------
__device__ __forceinline__ void cell_update(float acc[4][4][4], float cst[4][4],
                                            float4* hs4, int ty, int tx) {
    float ho[4][4];
    #pragma unroll
    for (int r = 0; r < 4; r++) {
        #pragma unroll
        for (int c = 0; c < 4; c++) {
            float i_ = sig_(acc[0][r][c]);
            float f_ = sig_(acc[1][r][c]);
            float g_ = tanh_(acc[2][r][c]);
            float o_ = sig_(acc[3][r][c]);
            float cn = f_ * cst[r][c] + i_ * g_;
            cst[r][c] = cn;
            ho[r][c] = o_ * tanh_(cn);
        }
    }
    #pragma unroll
    for (int c = 0; c < 4; c++)
        hs4[(tx * 4 + c) * ROWT + ty] = make_float4(ho[0][c], ho[1][c], ho[2][c], ho[3][c]);
}

// ---------------- layer 0: persistent, table-driven input ------------------
__global__ void __launch_bounds__(NTHR, 1)
layer0_kernel(const int* __restrict__ x) {
    extern __shared__ float sm[];
    float* ws = sm;                 // 40000 fp32: W_hh0^T [k][j]
    float* hs = sm + 40000;         // 5600 fp32:  h [k][b_local]
    int*   tok = (int*)(sm + 45600);
    float4* ws4 = (float4*)ws;
    float4* hs4 = (float4*)hs;
    const float4* Wt04 = (const float4*)g_Wt0;
    const float4* tab4 = (const float4*)g_table0;
    float4* gh14 = (float4*)g_h1;

    int tid = threadIdx.x, cta = blockIdx.x;
    int b0 = cta * BCTA;
    for (int i = tid; i < 10000; i += NTHR) ws4[i] = Wt04[i];
    for (int i = tid; i < 1400;  i += NTHR) hs4[i] = make_float4(0.f, 0.f, 0.f, 0.f);

    int ty = tid / COLT, tx = tid % COLT;
    bool act = tid < NACT;
    float cst[4][4] = {};
    float acc[4][4][4];

    for (int t = 0; t < TT; t++) {
        if (tid < BCTA) {
            int b = b0 + tid; if (b >= BB) b = BB - 1;
            tok[tid] = x[b * TT + t];
        }
        __syncthreads();
        if (act) {
            #pragma unroll
            for (int r = 0; r < 4; r++) {
                int tk = tok[ty * 4 + r];
                const float4* tp = tab4 + tk * 100 + tx;
                float4 a0 = tp[0], a1 = tp[25], a2 = tp[50], a3 = tp[75];
                acc[0][r][0] = a0.x; acc[0][r][1] = a0.y; acc[0][r][2] = a0.z; acc[0][r][3] = a0.w;
                acc[1][r][0] = a1.x; acc[1][r][1] = a1.y; acc[1][r][2] = a1.z; acc[1][r][3] = a1.w;
                acc[2][r][0] = a2.x; acc[2][r][1] = a2.y; acc[2][r][2] = a2.z; acc[2][r][3] = a2.w;
                acc[3][r][0] = a3.x; acc[3][r][1] = a3.y; acc[3][r][2] = a3.z; acc[3][r][3] = a3.w;
            }
            gemm_acc(ws4, hs4, ty, tx, acc);
        }
        __syncthreads();
        if (act) cell_update(acc, cst, hs4, ty, tx);
        __syncthreads();
        // coalesced copy-out of the h tile to global [t][k][b]
        int base = t * 204800 + cta * ROWT;
        for (int i = tid; i < 1400; i += NTHR) {
            int k = i / ROWT, bbq = i % ROWT;
            if (b0 + bbq * 4 + 3 < BB)
                gh14[base + k * 2048 + bbq] = hs4[i];
        }
    }
}

// ---------------- layer 1: per-step SMEM weight swap ------------------------
__global__ void __launch_bounds__(NTHR, 1)
layer1_kernel() {
    extern __shared__ float sm[];
    float* ws = sm;                 // 40000: current W^T
    float* hs = sm + 40000;         // 5600:  h state
    float* xs = sm + 45600;         // 5600:  layer0 output tile
    float* b1s = sm + 51200;        // 400:   bias
    float4* ws4 = (float4*)ws;
    float4* hs4 = (float4*)hs;
    float4* xs4 = (float4*)xs;
    const float4* Wi4 = (const float4*)g_Wt1i;
    const float4* Wh4 = (const float4*)g_Wt1h;
    const float4* gh14 = (const float4*)g_h1;

    int tid = threadIdx.x, cta = blockIdx.x;
    int b0 = cta * BCTA;
    for (int i = tid; i < 1400; i += NTHR) hs4[i] = make_float4(0.f, 0.f, 0.f, 0.f);
    for (int i = tid; i < G4;   i += NTHR) b1s[i] = g_b1[i];

    int ty = tid / COLT, tx = tid % COLT;
    bool act = tid < NACT;
    float cst[4][4] = {};
    float acc[4][4][4];

    for (int t = 0; t < TT; t++) {
        int base = t * 204800 + cta * ROWT;
        for (int i = tid; i < 1400; i += NTHR) {
            int k = i / ROWT, bbq = i % ROWT;
            xs4[i] = gh14[base + k * 2048 + bbq];
        }
        for (int i = tid; i < 10000; i += NTHR) ws4[i] = Wi4[i];
        __syncthreads();
        if (act) {
            #pragma unroll
            for (int g = 0; g < 4; g++) {
                float4 bv = *(const float4*)&b1s[g * 100 + tx * 4];
                #pragma unroll
                for (int r = 0; r < 4; r++) {
                    acc[g][r][0] = bv.x; acc[g][r][1] = bv.y;
                    acc[g][r][2] = bv.z; acc[g][r][3] = bv.w;
                }
            }
            gemm_acc(ws4, xs4, ty, tx, acc);   // input contribution
        }
        __syncthreads();
        for (int i = tid; i < 10000; i += NTHR) ws4[i] = Wh4[i];
        __syncthreads();
        if (act) gemm_acc(ws4, hs4, ty, tx, acc);  // recurrent contribution
        __syncthreads();
        if (act) cell_update(acc, cst, hs4, ty, tx);
        // no trailing sync needed: next-iter reads of hs are ordered by next sync
        __syncthreads();
    }
    // final h -> g_h2 [k][b]
    for (int i = tid; i < 1400; i += NTHR) {
        int k = i / ROWT, bbq = i % ROWT;
        if (b0 + bbq * 4 + 3 < BB)
            ((float4*)g_h2)[k * 2048 + cta * ROWT + bbq] = hs4[i];
    }
}

// ---------------- final FC: out[b][v] = h2[:,b]·fcW[v,:] + fcb[v] ----------
__global__ void __launch_bounds__(256, 1)
fc_kernel(const float* __restrict__ fcW, const float* __restrict__ fcb,
          float* __restrict__ out) {
    __shared__ float Ws[VV * HH];
    __shared__ float bs[VV];
    int tid = threadIdx.x;
    for (int i = tid; i < VV * HH; i += 256) Ws[i] = fcW[i];
    if (tid < VV) bs[tid] = fcb[tid];
    __syncthreads();

    int b = blockIdx.x * 256 + tid;
    float hr[HH];
    #pragma unroll
    for (int k = 0; k < HH; k++) hr[k] = g_h2[k * BB + b];

    const float4* Ws4 = (const float4*)Ws;
    float4* out4 = (float4*)out;
    #pragma unroll 1
    for (int v4 = 0; v4 < 25; v4++) {
        float a[4];
        #pragma unroll
        for (int q = 0; q < 4; q++) a[q] = bs[v4 * 4 + q];
        #pragma unroll
        for (int k4 = 0; k4 < 25; k4++) {
            #pragma unroll
            for (int q = 0; q < 4; q++) {
                float4 w = Ws4[(v4 * 4 + q) * 25 + k4];
                a[q] += hr[k4 * 4 + 0] * w.x + hr[k4 * 4 + 1] * w.y +
                        hr[k4 * 4 + 2] * w.z + hr[k4 * 4 + 3] * w.w;
            }
        }
        out4[b * 25 + v4] = make_float4(a[0], a[1], a[2], a[3]);
    }
}

// ---------------- launch ----------------------------------------------------
extern "C" void kernel_launch(void* const* d_in, const int* in_sizes, int n_in,
                              void* d_out, int out_size) {
    const int*   x     = (const int*)  d_in[0];
    const float* embed = (const float*)d_in[1];
    const float* Wih0  = (const float*)d_in[2];
    const float* Whh0  = (const float*)d_in[3];
    const float* bih0  = (const float*)d_in[4];
    const float* bhh0  = (const float*)d_in[5];
    const float* Wih1  = (const float*)d_in[6];
    const float* Whh1  = (const float*)d_in[7];
    const float* bih1  = (const float*)d_in[8];
    const float* bhh1  = (const float*)d_in[9];
    const float* fcW   = (const float*)d_in[10];
    const float* fcb   = (const float*)d_in[11];
    float* out = (float*)d_out;

    cudaFuncSetAttribute(layer0_kernel, cudaFuncAttributeMaxDynamicSharedMemorySize, SMEM0);
    cudaFuncSetAttribute(layer1_kernel, cudaFuncAttributeMaxDynamicSharedMemorySize, SMEM1);

    prep_kernel<<<160, 256>>>(embed, Wih0, Whh0, bih0, bhh0, Wih1, Whh1, bih1, bhh1);
    layer0_kernel<<<NCTA, NTHR, SMEM0>>>(x);
    layer1_kernel<<<NCTA, NTHR, SMEM1>>>();
    fc_kernel<<<BB / 256, 256>>>(fcW, fcb, out);
}

// round 2
// speedup vs baseline: 1.1541x; 1.1541x over previous
#include <cuda_runtime.h>

typedef unsigned long long u64;

// Problem constants
#define BB   8192
#define TT   80
#define HH   100
#define VV   100
#define G4   400
#define BCTA 56
#define ROWT 14      // ty groups (56/4) -- FAST index within warp
#define COLT 25      // tx groups (100/4)
#define NTHR 352
#define NACT 350
#define NCTA 147

#define SMEM_L0 ((40000 + 5600) * 4 + 64 * 4)   // Whh0^T + h + tok
#define SMEM_GX ((40000 + 5600 + 400) * 4)      // Wih1^T + x + bias
#define SMEM_L1 ((40000 + 5600) * 4)            // Whh1^T + h

// ---------------- device scratch ----------------
__device__ float g_table0[VV * G4];                 // layer0 gate table (incl bias)
__device__ float g_Wt0 [HH * G4];                   // W_hh0^T [k][j]
__device__ float g_Wt1i[HH * G4];                   // W_ih1^T [k][j]
__device__ float g_Wt1h[HH * G4];                   // W_hh1^T [k][j]
__device__ float g_b1  [G4];
__device__ float g_h1[(size_t)TT * HH * BB + 64];   // layer0 out [t][k][b]
__device__ u64   g_gx[(size_t)TT * 200 * BB + 64];  // layer1 gate input, packed c-pairs [t][jp][b]
__device__ float g_h2[(size_t)HH * BB + 64];        // final h [k][b]

// ---------------- activations ----------------
__device__ __forceinline__ float sig_(float x) {
    return __fdividef(1.f, 1.f + __expf(-x));
}
__device__ __forceinline__ float tanh_(float x) {
    float e = __expf(2.f * x);
    return 1.f - __fdividef(2.f, e + 1.f);
}

// ---------------- packed f32x2 primitives ----------------
__device__ __forceinline__ void ffma2(u64& d, u64 a, u64 b) {
    asm("fma.rn.f32x2 %0, %1, %2, %0;" : "+l"(d) : "l"(a), "l"(b));
}
__device__ __forceinline__ u64 pack2(float lo, float hi) {
    u64 r; asm("mov.b64 %0, {%1, %2};" : "=l"(r) : "f"(lo), "f"(hi)); return r;
}
__device__ __forceinline__ float2 unpack2(u64 v) {
    float2 f; asm("mov.b64 {%0, %1}, %2;" : "=f"(f.x), "=f"(f.y) : "l"(v)); return f;
}

// ---------------- prep ----------------
__global__ void prep_kernel(const float* __restrict__ embed,
                            const float* __restrict__ Wih0,
                            const float* __restrict__ Whh0,
                            const float* __restrict__ bih0,
                            const float* __restrict__ bhh0,
                            const float* __restrict__ Wih1,
                            const float* __restrict__ Whh1,
                            const float* __restrict__ bih1,
                            const float* __restrict__ bhh1) {
    for (int idx = blockIdx.x * blockDim.x + threadIdx.x; idx < HH * G4;
         idx += gridDim.x * blockDim.x) {
        int k = idx / G4;
        int j = idx % G4;
        g_Wt0 [k * G4 + j] = Whh0[j * HH + k];
        g_Wt1i[k * G4 + j] = Wih1[j * HH + k];
        g_Wt1h[k * G4 + j] = Whh1[j * HH + k];
        float s = bih0[j] + bhh0[j];
        #pragma unroll
        for (int e = 0; e < 8; e++) s += Wih0[j * 8 + e] * embed[k * 8 + e];
        g_table0[k * G4 + j] = s;
        if (idx < G4) g_b1[idx] = bih1[idx] + bhh1[idx];
    }
}

// ---------------- packed register-blocked GEMM accumulate -------------------
// acc[g][r][cp] (+)= W^T[k][g*100 + tx*4 + 2cp..2cp+1] * in[k][b0 + ty*4 + r]
__device__ __forceinline__ void gemm_acc2(const float4* __restrict__ ws4,
                                          const float4* __restrict__ in4,
                                          int ty, int tx, u64 acc[4][4][2]) {
    #pragma unroll 2
    for (int k = 0; k < HH; k++) {
        float4 h4 = in4[k * ROWT + ty];
        const ulonglong2* wr = (const ulonglong2*)(ws4 + k * 100 + tx);
        ulonglong2 wv[4];
        wv[0] = wr[0]; wv[1] = wr[25]; wv[2] = wr[50]; wv[3] = wr[75];
        u64 hp[4];
        hp[0] = pack2(h4.x, h4.x); hp[1] = pack2(h4.y, h4.y);
        hp[2] = pack2(h4.z, h4.z); hp[3] = pack2(h4.w, h4.w);
        #pragma unroll
        for (int g = 0; g < 4; g++) {
            #pragma unroll
            for (int r = 0; r < 4; r++) {
                ffma2(acc[g][r][0], wv[g].x, hp[r]);
                ffma2(acc[g][r][1], wv[g].y, hp[r]);
            }
        }
    }
}

// ---------------- LSTM cell elementwise + h store ---------------------------
__device__ __forceinline__ void cell_update2(u64 acc[4][4][2], float cst[4][4],
                                             float4* hs4, int ty, int tx) {
    float ho[4][4];
    #pragma unroll
    for (int r = 0; r < 4; r++) {
        #pragma unroll
        for (int cp = 0; cp < 2; cp++) {
            float2 iv = unpack2(acc[0][r][cp]);
            float2 fv = unpack2(acc[1][r][cp]);
            float2 gv = unpack2(acc[2][r][cp]);
            float2 ov = unpack2(acc[3][r][cp]);
            {
                float i_ = sig_(iv.x), f_ = sig_(fv.x), g_ = tanh_(gv.x), o_ = sig_(ov.x);
                float cn = f_ * cst[r][2 * cp] + i_ * g_;
                cst[r][2 * cp] = cn;
                ho[r][2 * cp] = o_ * tanh_(cn);
            }
            {
                float i_ = sig_(iv.y), f_ = sig_(fv.y), g_ = tanh_(gv.y), o_ = sig_(ov.y);
                float cn = f_ * cst[r][2 * cp + 1] + i_ * g_;
                cst[r][2 * cp + 1] = cn;
                ho[r][2 * cp + 1] = o_ * tanh_(cn);
            }
        }
    }
    #pragma unroll
    for (int c = 0; c < 4; c++)
        hs4[(tx * 4 + c) * ROWT + ty] = make_float4(ho[0][c], ho[1][c], ho[2][c], ho[3][c]);
}

// ---------------- layer 0: sequential, table-driven input -------------------
__global__ void __launch_bounds__(NTHR, 1)
layer0_kernel(const int* __restrict__ x) {
    extern __shared__ float sm[];
    float* ws = sm;
    float* hs = sm + 40000;
    int*   tok = (int*)(sm + 45600);
    float4* ws4 = (float4*)ws;
    float4* hs4 = (float4*)hs;
    float4* gh14 = (float4*)g_h1;

    int tid = threadIdx.x, cta = blockIdx.x;
    int b0 = cta * BCTA;
    for (int i = tid; i < 10000; i += NTHR) ws4[i] = ((const float4*)g_Wt0)[i];
    for (int i = tid; i < 1400;  i += NTHR) hs4[i] = make_float4(0.f, 0.f, 0.f, 0.f);

    int ty = tid % ROWT, tx = tid / ROWT;   // ty FAST within warp (weight broadcast)
    bool act = tid < NACT;
    float cst[4][4] = {};
    u64 acc[4][4][2];

    for (int t = 0; t < TT; t++) {
        if (tid < BCTA) {
            int b = b0 + tid; if (b >= BB) b = BB - 1;
            tok[tid] = x[b * TT + t];
        }
        __syncthreads();
        if (act) {
            #pragma unroll
            for (int r = 0; r < 4; r++) {
                int tk = tok[ty * 4 + r];
                const ulonglong2* tp = (const ulonglong2*)g_table0 + tk * 100 + tx;
                ulonglong2 a0 = tp[0], a1 = tp[25], a2 = tp[50], a3 = tp[75];
                acc[0][r][0] = a0.x; acc[0][r][1] = a0.y;
                acc[1][r][0] = a1.x; acc[1][r][1] = a1.y;
                acc[2][r][0] = a2.x; acc[2][r][1] = a2.y;
                acc[3][r][0] = a3.x; acc[3][r][1] = a3.y;
            }
            gemm_acc2(ws4, hs4, ty, tx, acc);
        }
        __syncthreads();
        if (act) cell_update2(acc, cst, hs4, ty, tx);
        __syncthreads();
        int base = t * 204800 + cta * ROWT;
        for (int i = tid; i < 1400; i += NTHR) {
            int k = i / ROWT, bq = i % ROWT;
            if (b0 + bq * 4 + 3 < BB)
                gh14[base + k * 2048 + bq] = hs4[i];
        }
    }
}

// ---------------- gx: parallel W_ih1 GEMM over all t, weights resident ------
__global__ void __launch_bounds__(NTHR, 1)
gx_kernel() {
    extern __shared__ float sm[];
    float* ws = sm;
    float* xs = sm + 40000;
    float* b1s = sm + 45600;
    float4* ws4 = (float4*)ws;
    float4* xs4 = (float4*)xs;
    const float4* gh14 = (const float4*)g_h1;

    int tid = threadIdx.x, cta = blockIdx.x;
    int b0 = cta * BCTA;
    for (int i = tid; i < 10000; i += NTHR) ws4[i] = ((const float4*)g_Wt1i)[i];
    for (int i = tid; i < G4;    i += NTHR) b1s[i] = g_b1[i];

    int ty = tid % ROWT, tx = tid / ROWT;
    bool act = tid < NACT;
    bool strow = (b0 + ty * 4 + 3) < BB;
    u64 acc[4][4][2];

    for (int t = 0; t < TT; t++) {
        int base = t * 204800 + cta * ROWT;
        for (int i = tid; i < 1400; i += NTHR) {
            int k = i / ROWT, bq = i % ROWT;
            xs4[i] = gh14[base + k * 2048 + bq];
        }
        __syncthreads();
        if (act) {
            #pragma unroll
            for (int g = 0; g < 4; g++) {
                ulonglong2 bv = *(const ulonglong2*)(b1s + g * 100 + tx * 4);
                #pragma unroll
                for (int r = 0; r < 4; r++) { acc[g][r][0] = bv.x; acc[g][r][1] = bv.y; }
            }
            gemm_acc2(ws4, xs4, ty, tx, acc);
            if (strow) {
                size_t tb = (size_t)t * 200 * BB;
                #pragma unroll
                for (int g = 0; g < 4; g++) {
                    #pragma unroll
                    for (int cp = 0; cp < 2; cp++) {
                        int jp = g * 50 + tx * 2 + cp;
                        u64* dst = g_gx + tb + (size_t)jp * BB + b0 + ty * 4;
                        ((ulonglong2*)dst)[0] = make_ulonglong2(acc[g][0][cp], acc[g][1][cp]);
                        ((ulonglong2*)dst)[1] = make_ulonglong2(acc[g][2][cp], acc[g][3][cp]);
                    }
                }
            }
        }
        __syncthreads();
    }
}

// ---------------- layer 1: sequential, W_hh1 resident ------------------------
__global__ void __launch_bounds__(NTHR, 1)
layer1_kernel() {
    extern __shared__ float sm[];
    float* ws = sm;
    float* hs = sm + 40000;
    float4* ws4 = (float4*)ws;
    float4* hs4 = (float4*)hs;

    int tid = threadIdx.x, cta = blockIdx.x;
    int b0 = cta * BCTA;
    for (int i = tid; i < 10000; i += NTHR) ws4[i] = ((const float4*)g_Wt1h)[i];
    for (int i = tid; i < 1400;  i += NTHR) hs4[i] = make_float4(0.f, 0.f, 0.f, 0.f);
    __syncthreads();

    int ty = tid % ROWT, tx = tid / ROWT;
    bool act = tid < NACT;
    float cst[4][4] = {};
    u64 acc[4][4][2];

    for (int t = 0; t < TT; t++) {
        if (act) {
            size_t tb = (size_t)t * 200 * BB;
            #pragma unroll
            for (int g = 0; g < 4; g++) {
                #pragma unroll
                for (int cp = 0; cp < 2; cp++) {
                    int jp = g * 50 + tx * 2 + cp;
                    const u64* src = g_gx + tb + (size_t)jp * BB + b0 + ty * 4;
                    ulonglong2 q01 = ((const ulonglong2*)src)[0];
                    ulonglong2 q23 = ((const ulonglong2*)src)[1];
                    acc[g][0][cp] = q01.x; acc[g][1][cp] = q01.y;
                    acc[g][2][cp] = q23.x; acc[g][3][cp] = q23.y;
                }
            }
            gemm_acc2(ws4, hs4, ty, tx, acc);
        }
        __syncthreads();
        if (act) cell_update2(acc, cst, hs4, ty, tx);
        __syncthreads();
    }
    for (int i = tid; i < 1400; i += NTHR) {
        int k = i / ROWT, bq = i % ROWT;
        if (b0 + bq * 4 + 3 < BB)
            ((float4*)g_h2)[k * 2048 + cta * ROWT + bq] = hs4[i];
    }
}

// ---------------- final FC ---------------------------------------------------
__global__ void __launch_bounds__(256, 1)
fc_kernel(const float* __restrict__ fcW, const float* __restrict__ fcb,
          float* __restrict__ out) {
    __shared__ float Ws[VV * HH];
    __shared__ float bs[VV];
    int tid = threadIdx.x;
    for (int i = tid; i < VV * HH; i += 256) Ws[i] = fcW[i];
    if (tid < VV) bs[tid] = fcb[tid];
    __syncthreads();

    int b = blockIdx.x * 256 + tid;
    float hr[HH];
    #pragma unroll
    for (int k = 0; k < HH; k++) hr[k] = g_h2[k * BB + b];

    const float4* Ws4 = (const float4*)Ws;
    float4* out4 = (float4*)out;
    #pragma unroll 1
    for (int v4 = 0; v4 < 25; v4++) {
        float a[4];
        #pragma unroll
        for (int q = 0; q < 4; q++) a[q] = bs[v4 * 4 + q];
        #pragma unroll
        for (int k4 = 0; k4 < 25; k4++) {
            #pragma unroll
            for (int q = 0; q < 4; q++) {
                float4 w = Ws4[(v4 * 4 + q) * 25 + k4];
                a[q] += hr[k4 * 4 + 0] * w.x + hr[k4 * 4 + 1] * w.y +
                        hr[k4 * 4 + 2] * w.z + hr[k4 * 4 + 3] * w.w;
            }
        }
        out4[b * 25 + v4] = make_float4(a[0], a[1], a[2], a[3]);
    }
}

// ---------------- launch ------------------------------------------------------
extern "C" void kernel_launch(void* const* d_in, const int* in_sizes, int n_in,
                              void* d_out, int out_size) {
    const int*   x     = (const int*)  d_in[0];
    const float* embed = (const float*)d_in[1];
    const float* Wih0  = (const float*)d_in[2];
    const float* Whh0  = (const float*)d_in[3];
    const float* bih0  = (const float*)d_in[4];
    const float* bhh0  = (const float*)d_in[5];
    const float* Wih1  = (const float*)d_in[6];
    const float* Whh1  = (const float*)d_in[7];
    const float* bih1  = (const float*)d_in[8];
    const float* bhh1  = (const float*)d_in[9];
    const float* fcW   = (const float*)d_in[10];
    const float* fcb   = (const float*)d_in[11];
    float* out = (float*)d_out;

    cudaFuncSetAttribute(layer0_kernel, cudaFuncAttributeMaxDynamicSharedMemorySize, SMEM_L0);
    cudaFuncSetAttribute(gx_kernel,     cudaFuncAttributeMaxDynamicSharedMemorySize, SMEM_GX);
    cudaFuncSetAttribute(layer1_kernel, cudaFuncAttributeMaxDynamicSharedMemorySize, SMEM_L1);

    prep_kernel<<<160, 256>>>(embed, Wih0, Whh0, bih0, bhh0, Wih1, Whh1, bih1, bhh1);
    layer0_kernel<<<NCTA, NTHR, SMEM_L0>>>(x);
    gx_kernel<<<NCTA, NTHR, SMEM_GX>>>();
    layer1_kernel<<<NCTA, NTHR, SMEM_L1>>>();
    fc_kernel<<<BB / 256, 256>>>(fcW, fcb, out);
}

// round 3
// speedup vs baseline: 1.1561x; 1.0018x over previous
#include <cuda_runtime.h>

typedef unsigned long long u64;

// Problem constants
#define BB   8192
#define TT   80
#define HH   100
#define VV   100
#define G4   400
#define BCTA 56
#define ROWT 14      // ty groups (56/4) -- FAST index within warp
#define COLT 25      // tx groups (100/4)
#define NTHR 352
#define NACT 350
#define NCTA 147

#define SMEM_L0 ((40000 + 5600) * 4 + 64 * 4)   // Whh0^T + h + tok
#define SMEM_GX ((40000 + 5600 + 400) * 4)      // Wih1^T + x + bias
#define SMEM_L1 ((40000 + 5600) * 4)            // Whh1^T + h

// ---------------- device scratch ----------------
__device__ float g_table0[VV * G4];                 // layer0 gate table (incl bias)
__device__ float g_Wt0 [HH * G4];                   // W_hh0^T [k][j]
__device__ float g_Wt1i[HH * G4];                   // W_ih1^T [k][j]
__device__ float g_Wt1h[HH * G4];                   // W_hh1^T [k][j]
__device__ float g_b1  [G4];
__device__ float g_h1[(size_t)TT * HH * BB + 64];   // layer0 out [t][k][b]
__device__ u64   g_gx[(size_t)TT * 200 * BB + 64];  // layer1 gate input, packed c-pairs [t][jp][b]
__device__ float g_h2[(size_t)HH * BB + 64];        // final h [k][b]

// ---------------- activations ----------------
__device__ __forceinline__ float sig_(float x) {
    return __fdividef(1.f, 1.f + __expf(-x));
}
__device__ __forceinline__ float tanh_(float x) {
    float e = __expf(2.f * x);
    return 1.f - __fdividef(2.f, e + 1.f);
}

// ---------------- packed f32x2 primitives ----------------
__device__ __forceinline__ void ffma2(u64& d, u64 a, u64 b) {
    asm("fma.rn.f32x2 %0, %1, %2, %0;" : "+l"(d) : "l"(a), "l"(b));
}
__device__ __forceinline__ u64 pack2(float lo, float hi) {
    u64 r; asm("mov.b64 %0, {%1, %2};" : "=l"(r) : "f"(lo), "f"(hi)); return r;
}
__device__ __forceinline__ float2 unpack2(u64 v) {
    float2 f; asm("mov.b64 {%0, %1}, %2;" : "=f"(f.x), "=f"(f.y) : "l"(v)); return f;
}

// ---------------- prep ----------------
__global__ void prep_kernel(const float* __restrict__ embed,
                            const float* __restrict__ Wih0,
                            const float* __restrict__ Whh0,
                            const float* __restrict__ bih0,
                            const float* __restrict__ bhh0,
                            const float* __restrict__ Wih1,
                            const float* __restrict__ Whh1,
                            const float* __restrict__ bih1,
                            const float* __restrict__ bhh1) {
    for (int idx = blockIdx.x * blockDim.x + threadIdx.x; idx < HH * G4;
         idx += gridDim.x * blockDim.x) {
        int k = idx / G4;
        int j = idx % G4;
        g_Wt0 [k * G4 + j] = Whh0[j * HH + k];
        g_Wt1i[k * G4 + j] = Wih1[j * HH + k];
        g_Wt1h[k * G4 + j] = Whh1[j * HH + k];
        float s = bih0[j] + bhh0[j];
        #pragma unroll
        for (int e = 0; e < 8; e++) s += Wih0[j * 8 + e] * embed[k * 8 + e];
        g_table0[k * G4 + j] = s;
        if (idx < G4) g_b1[idx] = bih1[idx] + bhh1[idx];
    }
}

// ---------------- packed register-blocked GEMM accumulate -------------------
// acc[g][r][cp] (+)= W^T[k][g*100 + tx*4 + 2cp..2cp+1] * in[k][b0 + ty*4 + r]
__device__ __forceinline__ void gemm_acc2(const float4* __restrict__ ws4,
                                          const float4* __restrict__ in4,
                                          int ty, int tx, u64 acc[4][4][2]) {
    #pragma unroll 2
    for (int k = 0; k < HH; k++) {
        float4 h4 = in4[k * ROWT + ty];
        const ulonglong2* wr = (const ulonglong2*)(ws4 + k * 100 + tx);
        ulonglong2 wv[4];
        wv[0] = wr[0]; wv[1] = wr[25]; wv[2] = wr[50]; wv[3] = wr[75];
        u64 hp[4];
        hp[0] = pack2(h4.x, h4.x); hp[1] = pack2(h4.y, h4.y);
        hp[2] = pack2(h4.z, h4.z); hp[3] = pack2(h4.w, h4.w);
        #pragma unroll
        for (int g = 0; g < 4; g++) {
            #pragma unroll
            for (int r = 0; r < 4; r++) {
                ffma2(acc[g][r][0], wv[g].x, hp[r]);
                ffma2(acc[g][r][1], wv[g].y, hp[r]);
            }
        }
    }
}

// ---------------- LSTM cell elementwise + h store ---------------------------
__device__ __forceinline__ void cell_update2(u64 acc[4][4][2], float cst[4][4],
                                             float4* hs4, int ty, int tx) {
    float ho[4][4];
    #pragma unroll
    for (int r = 0; r < 4; r++) {
        #pragma unroll
        for (int cp = 0; cp < 2; cp++) {
            float2 iv = unpack2(acc[0][r][cp]);
            float2 fv = unpack2(acc[1][r][cp]);
            float2 gv = unpack2(acc[2][r][cp]);
            float2 ov = unpack2(acc[3][r][cp]);
            {
                float i_ = sig_(iv.x), f_ = sig_(fv.x), g_ = tanh_(gv.x), o_ = sig_(ov.x);
                float cn = f_ * cst[r][2 * cp] + i_ * g_;
                cst[r][2 * cp] = cn;
                ho[r][2 * cp] = o_ * tanh_(cn);
            }
            {
                float i_ = sig_(iv.y), f_ = sig_(fv.y), g_ = tanh_(gv.y), o_ = sig_(ov.y);
                float cn = f_ * cst[r][2 * cp + 1] + i_ * g_;
                cst[r][2 * cp + 1] = cn;
                ho[r][2 * cp + 1] = o_ * tanh_(cn);
            }
        }
    }
    #pragma unroll
    for (int c = 0; c < 4; c++)
        hs4[(tx * 4 + c) * ROWT + ty] = make_float4(ho[0][c], ho[1][c], ho[2][c], ho[3][c]);
}

// ---------------- layer 0: sequential, table-driven input -------------------
__global__ void __launch_bounds__(NTHR, 1)
layer0_kernel(const int* __restrict__ x) {
    extern __shared__ float sm[];
    float* ws = sm;
    float* hs = sm + 40000;
    int*   tok = (int*)(sm + 45600);
    float4* ws4 = (float4*)ws;
    float4* hs4 = (float4*)hs;
    float4* gh14 = (float4*)g_h1;

    int tid = threadIdx.x, cta = blockIdx.x;
    int b0 = cta * BCTA;
    for (int i = tid; i < 10000; i += NTHR) ws4[i] = ((const float4*)g_Wt0)[i];
    for (int i = tid; i < 1400;  i += NTHR) hs4[i] = make_float4(0.f, 0.f, 0.f, 0.f);

    int ty = tid % ROWT, tx = tid / ROWT;   // ty FAST within warp (weight broadcast)
    bool act = tid < NACT;
    float cst[4][4] = {};
    u64 acc[4][4][2];

    for (int t = 0; t < TT; t++) {
        if (tid < BCTA) {
            int b = b0 + tid; if (b >= BB) b = BB - 1;
            tok[tid] = x[b * TT + t];
        }
        __syncthreads();
        if (act) {
            #pragma unroll
            for (int r = 0; r < 4; r++) {
                int tk = tok[ty * 4 + r];
                const ulonglong2* tp = (const ulonglong2*)g_table0 + tk * 100 + tx;
                ulonglong2 a0 = tp[0], a1 = tp[25], a2 = tp[50], a3 = tp[75];
                acc[0][r][0] = a0.x; acc[0][r][1] = a0.y;
                acc[1][r][0] = a1.x; acc[1][r][1] = a1.y;
                acc[2][r][0] = a2.x; acc[2][r][1] = a2.y;
                acc[3][r][0] = a3.x; acc[3][r][1] = a3.y;
            }
            gemm_acc2(ws4, hs4, ty, tx, acc);
        }
        __syncthreads();
        if (act) cell_update2(acc, cst, hs4, ty, tx);
        __syncthreads();
        int base = t * 204800 + cta * ROWT;
        for (int i = tid; i < 1400; i += NTHR) {
            int k = i / ROWT, bq = i % ROWT;
            if (b0 + bq * 4 + 3 < BB)
                gh14[base + k * 2048 + bq] = hs4[i];
        }
    }
}

// ---------------- gx: parallel W_ih1 GEMM over all t, weights resident ------
__global__ void __launch_bounds__(NTHR, 1)
gx_kernel() {
    extern __shared__ float sm[];
    float* ws = sm;
    float* xs = sm + 40000;
    float* b1s = sm + 45600;
    float4* ws4 = (float4*)ws;
    float4* xs4 = (float4*)xs;
    const float4* gh14 = (const float4*)g_h1;

    int tid = threadIdx.x, cta = blockIdx.x;
    int b0 = cta * BCTA;
    for (int i = tid; i < 10000; i += NTHR) ws4[i] = ((const float4*)g_Wt1i)[i];
    for (int i = tid; i < G4;    i += NTHR) b1s[i] = g_b1[i];

    int ty = tid % ROWT, tx = tid / ROWT;
    bool act = tid < NACT;
    bool strow = (b0 + ty * 4 + 3) < BB;
    u64 acc[4][4][2];

    for (int t = 0; t < TT; t++) {
        int base = t * 204800 + cta * ROWT;
        for (int i = tid; i < 1400; i += NTHR) {
            int k = i / ROWT, bq = i % ROWT;
            xs4[i] = gh14[base + k * 2048 + bq];
        }
        __syncthreads();
        if (act) {
            #pragma unroll
            for (int g = 0; g < 4; g++) {
                ulonglong2 bv = *(const ulonglong2*)(b1s + g * 100 + tx * 4);
                #pragma unroll
                for (int r = 0; r < 4; r++) { acc[g][r][0] = bv.x; acc[g][r][1] = bv.y; }
            }
            gemm_acc2(ws4, xs4, ty, tx, acc);
            if (strow) {
                size_t tb = (size_t)t * 200 * BB;
                #pragma unroll
                for (int g = 0; g < 4; g++) {
                    #pragma unroll
                    for (int cp = 0; cp < 2; cp++) {
                        int jp = g * 50 + tx * 2 + cp;
                        u64* dst = g_gx + tb + (size_t)jp * BB + b0 + ty * 4;
                        ((ulonglong2*)dst)[0] = make_ulonglong2(acc[g][0][cp], acc[g][1][cp]);
                        ((ulonglong2*)dst)[1] = make_ulonglong2(acc[g][2][cp], acc[g][3][cp]);
                    }
                }
            }
        }
        __syncthreads();
    }
}

// ---------------- layer 1: sequential, W_hh1 resident ------------------------
__global__ void __launch_bounds__(NTHR, 1)
layer1_kernel() {
    extern __shared__ float sm[];
    float* ws = sm;
    float* hs = sm + 40000;
    float4* ws4 = (float4*)ws;
    float4* hs4 = (float4*)hs;

    int tid = threadIdx.x, cta = blockIdx.x;
    int b0 = cta * BCTA;
    for (int i = tid; i < 10000; i += NTHR) ws4[i] = ((const float4*)g_Wt1h)[i];
    for (int i = tid; i < 1400;  i += NTHR) hs4[i] = make_float4(0.f, 0.f, 0.f, 0.f);
    __syncthreads();

    int ty = tid % ROWT, tx = tid / ROWT;
    bool act = tid < NACT;
    float cst[4][4] = {};
    u64 acc[4][4][2];

    for (int t = 0; t < TT; t++) {
        if (act) {
            size_t tb = (size_t)t * 200 * BB;
            #pragma unroll
            for (int g = 0; g < 4; g++) {
                #pragma unroll
                for (int cp = 0; cp < 2; cp++) {
                    int jp = g * 50 + tx * 2 + cp;
                    const u64* src = g_gx + tb + (size_t)jp * BB + b0 + ty * 4;
                    ulonglong2 q01 = ((const ulonglong2*)src)[0];
                    ulonglong2 q23 = ((const ulonglong2*)src)[1];
                    acc[g][0][cp] = q01.x; acc[g][1][cp] = q01.y;
                    acc[g][2][cp] = q23.x; acc[g][3][cp] = q23.y;
                }
            }
            gemm_acc2(ws4, hs4, ty, tx, acc);
        }
        __syncthreads();
        if (act) cell_update2(acc, cst, hs4, ty, tx);
        __syncthreads();
    }
    for (int i = tid; i < 1400; i += NTHR) {
        int k = i / ROWT, bq = i % ROWT;
        if (b0 + bq * 4 + 3 < BB)
            ((float4*)g_h2)[k * 2048 + cta * ROWT + bq] = hs4[i];
    }
}

// ---------------- final FC ---------------------------------------------------
__global__ void __launch_bounds__(256, 1)
fc_kernel(const float* __restrict__ fcW, const float* __restrict__ fcb,
          float* __restrict__ out) {
    __shared__ float Ws[VV * HH];
    __shared__ float bs[VV];
    int tid = threadIdx.x;
    for (int i = tid; i < VV * HH; i += 256) Ws[i] = fcW[i];
    if (tid < VV) bs[tid] = fcb[tid];
    __syncthreads();

    int b = blockIdx.x * 256 + tid;
    float hr[HH];
    #pragma unroll
    for (int k = 0; k < HH; k++) hr[k] = g_h2[k * BB + b];

    const float4* Ws4 = (const float4*)Ws;
    float4* out4 = (float4*)out;
    #pragma unroll 1
    for (int v4 = 0; v4 < 25; v4++) {
        float a[4];
        #pragma unroll
        for (int q = 0; q < 4; q++) a[q] = bs[v4 * 4 + q];
        #pragma unroll
        for (int k4 = 0; k4 < 25; k4++) {
            #pragma unroll
            for (int q = 0; q < 4; q++) {
                float4 w = Ws4[(v4 * 4 + q) * 25 + k4];
                a[q] += hr[k4 * 4 + 0] * w.x + hr[k4 * 4 + 1] * w.y +
                        hr[k4 * 4 + 2] * w.z + hr[k4 * 4 + 3] * w.w;
            }
        }
        out4[b * 25 + v4] = make_float4(a[0], a[1], a[2], a[3]);
    }
}

// ---------------- launch ------------------------------------------------------
extern "C" void kernel_launch(void* const* d_in, const int* in_sizes, int n_in,
                              void* d_out, int out_size) {
    const int*   x     = (const int*)  d_in[0];
    const float* embed = (const float*)d_in[1];
    const float* Wih0  = (const float*)d_in[2];
    const float* Whh0  = (const float*)d_in[3];
    const float* bih0  = (const float*)d_in[4];
    const float* bhh0  = (const float*)d_in[5];
    const float* Wih1  = (const float*)d_in[6];
    const float* Whh1  = (const float*)d_in[7];
    const float* bih1  = (const float*)d_in[8];
    const float* bhh1  = (const float*)d_in[9];
    const float* fcW   = (const float*)d_in[10];
    const float* fcb   = (const float*)d_in[11];
    float* out = (float*)d_out;

    cudaFuncSetAttribute(layer0_kernel, cudaFuncAttributeMaxDynamicSharedMemorySize, SMEM_L0);
    cudaFuncSetAttribute(gx_kernel,     cudaFuncAttributeMaxDynamicSharedMemorySize, SMEM_GX);
    cudaFuncSetAttribute(layer1_kernel, cudaFuncAttributeMaxDynamicSharedMemorySize, SMEM_L1);

    prep_kernel<<<160, 256>>>(embed, Wih0, Whh0, bih0, bhh0, Wih1, Whh1, bih1, bhh1);
    layer0_kernel<<<NCTA, NTHR, SMEM_L0>>>(x);
    gx_kernel<<<NCTA, NTHR, SMEM_GX>>>();
    layer1_kernel<<<NCTA, NTHR, SMEM_L1>>>();
    fc_kernel<<<BB / 256, 256>>>(fcW, fcb, out);
}